// round 8
// baseline (speedup 1.0000x reference)
#include <cuda_runtime.h>
#include <math.h>

#define NT 64
#define NH 2048
#define NI 1408
#define NE 32
#define NK 4
#define NPAIR (NT * NK)
#define MAXSLOT (NPAIR + NE)   // per-expert even padding adds <=1 slot each

// ---- scratch (device globals: no allocation allowed) ----
__device__ int   d_expert_count[NE];
__device__ int   d_expert_start[NE];     // even per-expert starts
__device__ int   d_total_slots;
__device__ int   d_pair_token[MAXSLOT];          // slot -> token (pads -> 0)
__device__ int   d_pair_idx[NT * NK];            // (token,k) -> slot
__device__ float d_topk_w[NT * NK];              // routing weights
__device__ float d_xg2[(MAXSLOT + 2) * NH];      // x, token-PAIR interleaved: [g][k][2]
__device__ float d_mixed2[(MAXSLOT + 2) * NI];   // silu(g)*u, same interleaving
__device__ float d_pair_out[MAXSLOT * NH];       // down output per slot

// ---- packed f32x2 helpers (FFMA2: PTX-only on sm_103a) ----
__device__ __forceinline__ unsigned long long pk2(float lo, float hi) {
    unsigned long long r;
    asm("mov.b64 %0, {%1, %2};" : "=l"(r) : "f"(lo), "f"(hi));
    return r;
}
__device__ __forceinline__ void upk2(unsigned long long v, float& lo, float& hi) {
    asm("mov.b64 {%0, %1}, %2;" : "=f"(lo), "=f"(hi) : "l"(v));
}
__device__ __forceinline__ unsigned long long fma2(unsigned long long a,
                                                   unsigned long long b,
                                                   unsigned long long c) {
    unsigned long long d;
    asm("fma.rn.f32x2 %0, %1, %2, %3;" : "=l"(d) : "l"(a), "l"(b), "l"(c));
    return d;
}
__device__ __forceinline__ unsigned long long add2(unsigned long long a,
                                                   unsigned long long b) {
    unsigned long long d;
    asm("add.rn.f32x2 %0, %1, %2;" : "=l"(d) : "l"(a), "l"(b));
    return d;
}

// ============================================================
// Kernel 1: routing. One block, one thread per token.
// ============================================================
__global__ void route_kernel(const float* __restrict__ logits) {
    __shared__ int s_count[NE];
    __shared__ int s_start[NE];
    __shared__ int s_slot[NE];
    const int t = threadIdx.x;

    if (t < NE) { s_count[t] = 0; s_slot[t] = 0; }
    __syncthreads();

    float v[NE];
#pragma unroll
    for (int e = 0; e < NE; e++) v[e] = logits[t * NE + e];

    int ids[NK];
    float vals[NK];
#pragma unroll
    for (int k = 0; k < NK; k++) {
        int best = 0;
        float bv = -1e30f;
#pragma unroll
        for (int e = 0; e < NE; e++) {
            if (v[e] > bv) { bv = v[e]; best = e; }  // strict > : lowest index wins ties
        }
        ids[k] = best;
        vals[k] = bv;
        v[best] = -1e30f;
    }

    float m = vals[0];
    float w[NK];
    float s = 0.f;
#pragma unroll
    for (int k = 0; k < NK; k++) { w[k] = expf(vals[k] - m); s += w[k]; }
    float inv = 1.f / s;
#pragma unroll
    for (int k = 0; k < NK; k++) d_topk_w[t * NK + k] = w[k] * inv;

#pragma unroll
    for (int k = 0; k < NK; k++) atomicAdd(&s_count[ids[k]], 1);
    __syncthreads();

    if (t == 0) {
        int off = 0;
        for (int e = 0; e < NE; e++) {
            s_start[e] = off;
            off += (s_count[e] + 1) & ~1;   // pad each expert region to even
        }
        d_total_slots = off;
    }
    __syncthreads();

#pragma unroll
    for (int k = 0; k < NK; k++) {
        int slot = atomicAdd(&s_slot[ids[k]], 1);
        int p = s_start[ids[k]] + slot;
        d_pair_token[p] = t;
        d_pair_idx[t * NK + k] = p;
    }
    if (t < NE) {
        d_expert_count[t] = s_count[t];
        d_expert_start[t] = s_start[t];
        if (s_count[t] & 1)                  // fill the pad slot with token 0
            d_pair_token[s_start[t] + s_count[t]] = 0;
    }
}

// ============================================================
// Kernel 1b: gather x rows, token-pair interleaved.
//   d_xg2[(p&~1)*NH + 2k + (p&1)] = x[token(p)][k]
// ============================================================
__global__ void gather_kernel(const float* __restrict__ x) {
    const int p = blockIdx.x;
    if (p >= d_total_slots) return;
    const int t = d_pair_token[p];
    const int g = p & ~1;
    const int par = p & 1;
    const float* __restrict__ src = x + (size_t)t * NH;
    float* __restrict__ dst = d_xg2 + (size_t)g * NH + par;
    for (int k = threadIdx.x; k < NH; k += blockDim.x)
        dst[2 * k] = src[k];
}

// ============================================================
// Kernel 2: gate/up matvecs + SiLU. One warp: 2 inter rows
// (gate+up = 4 weight streams), P token-pairs in FFMA2 halves.
// Fully unrolled, software-pipelined k-loop (16 iters).
// ============================================================
template<int P>   // token pairs this pass, 1..4
__device__ __forceinline__ void gateup_body(
    const int nc, const int slot0,
    const float* __restrict__ wg0, const float* __restrict__ wg1,
    const float* __restrict__ wu0, const float* __restrict__ wu1,
    const int i0, const int lane)
{
    constexpr int ITERS = NH / 4 / 32;   // 16, compile-time

    unsigned long long ag0[P], ag1[P], au0[P], au1[P];
#pragma unroll
    for (int p = 0; p < P; p++) { ag0[p] = 0ull; ag1[p] = 0ull; au0[p] = 0ull; au1[p] = 0ull; }

    const float4* __restrict__ g0 = (const float4*)wg0;
    const float4* __restrict__ g1 = (const float4*)wg1;
    const float4* __restrict__ u0 = (const float4*)wu0;
    const float4* __restrict__ u1 = (const float4*)wu1;

    const ulonglong2* __restrict__ xp[P];
#pragma unroll
    for (int p = 0; p < P; p++)
        xp[p] = (const ulonglong2*)(d_xg2 + (size_t)(slot0 + 2 * p) * NH);

    // stage registers
    float4 a0, a1, b0, b1;
    ulonglong2 xlo[P], xhi[P];
    {
        const int kq = lane;
        a0 = __ldg(&g0[kq]); a1 = __ldg(&g1[kq]);
        b0 = __ldg(&u0[kq]); b1 = __ldg(&u1[kq]);
#pragma unroll
        for (int p = 0; p < P; p++) {
            xlo[p] = __ldg(&xp[p][2 * kq]);
            xhi[p] = __ldg(&xp[p][2 * kq + 1]);
        }
    }

#pragma unroll
    for (int it = 0; it < ITERS; it++) {
        // stash current stage
        const float4 ca0 = a0, ca1 = a1, cb0 = b0, cb1 = b1;
        ulonglong2 cxlo[P], cxhi[P];
#pragma unroll
        for (int p = 0; p < P; p++) { cxlo[p] = xlo[p]; cxhi[p] = xhi[p]; }

        // issue next-iteration loads BEFORE consuming current
        if (it + 1 < ITERS) {
            const int kq = lane + 32 * (it + 1);
            a0 = __ldg(&g0[kq]); a1 = __ldg(&g1[kq]);
            b0 = __ldg(&u0[kq]); b1 = __ldg(&u1[kq]);
#pragma unroll
            for (int p = 0; p < P; p++) {
                xlo[p] = __ldg(&xp[p][2 * kq]);
                xhi[p] = __ldg(&xp[p][2 * kq + 1]);
            }
        }

        const unsigned long long A0x = pk2(ca0.x, ca0.x), A0y = pk2(ca0.y, ca0.y),
                                 A0z = pk2(ca0.z, ca0.z), A0w = pk2(ca0.w, ca0.w);
        const unsigned long long A1x = pk2(ca1.x, ca1.x), A1y = pk2(ca1.y, ca1.y),
                                 A1z = pk2(ca1.z, ca1.z), A1w = pk2(ca1.w, ca1.w);
        const unsigned long long B0x = pk2(cb0.x, cb0.x), B0y = pk2(cb0.y, cb0.y),
                                 B0z = pk2(cb0.z, cb0.z), B0w = pk2(cb0.w, cb0.w);
        const unsigned long long B1x = pk2(cb1.x, cb1.x), B1y = pk2(cb1.y, cb1.y),
                                 B1z = pk2(cb1.z, cb1.z), B1w = pk2(cb1.w, cb1.w);
#pragma unroll
        for (int p = 0; p < P; p++) {
            ag0[p] = fma2(A0x, cxlo[p].x, ag0[p]); ag0[p] = fma2(A0y, cxlo[p].y, ag0[p]);
            ag0[p] = fma2(A0z, cxhi[p].x, ag0[p]); ag0[p] = fma2(A0w, cxhi[p].y, ag0[p]);
            ag1[p] = fma2(A1x, cxlo[p].x, ag1[p]); ag1[p] = fma2(A1y, cxlo[p].y, ag1[p]);
            ag1[p] = fma2(A1z, cxhi[p].x, ag1[p]); ag1[p] = fma2(A1w, cxhi[p].y, ag1[p]);
            au0[p] = fma2(B0x, cxlo[p].x, au0[p]); au0[p] = fma2(B0y, cxlo[p].y, au0[p]);
            au0[p] = fma2(B0z, cxhi[p].x, au0[p]); au0[p] = fma2(B0w, cxhi[p].y, au0[p]);
            au1[p] = fma2(B1x, cxlo[p].x, au1[p]); au1[p] = fma2(B1y, cxlo[p].y, au1[p]);
            au1[p] = fma2(B1z, cxhi[p].x, au1[p]); au1[p] = fma2(B1w, cxhi[p].y, au1[p]);
        }
    }

#pragma unroll
    for (int p = 0; p < P; p++) {
#pragma unroll
        for (int o = 16; o > 0; o >>= 1) {
            ag0[p] = add2(ag0[p], __shfl_down_sync(0xFFFFFFFFu, ag0[p], o));
            ag1[p] = add2(ag1[p], __shfl_down_sync(0xFFFFFFFFu, ag1[p], o));
            au0[p] = add2(au0[p], __shfl_down_sync(0xFFFFFFFFu, au0[p], o));
            au1[p] = add2(au1[p], __shfl_down_sync(0xFFFFFFFFu, au1[p], o));
        }
        if (lane == 0 && 2 * p < nc) {
            float gA, gB, uA, uB;
            const int g = slot0 + 2 * p;   // even group
            upk2(ag0[p], gA, gB); upk2(au0[p], uA, uB);
            float* mo0 = d_mixed2 + (size_t)g * NI + 2 * i0;
            mo0[0] = (gA / (1.f + expf(-gA))) * uA;
            mo0[1] = (gB / (1.f + expf(-gB))) * uB;
            upk2(ag1[p], gA, gB); upk2(au1[p], uA, uB);
            float* mo1 = d_mixed2 + (size_t)g * NI + 2 * (i0 + 1);
            mo1[0] = (gA / (1.f + expf(-gA))) * uA;
            mo1[1] = (gB / (1.f + expf(-gB))) * uB;
        }
    }
}

__global__ void __launch_bounds__(128) gateup_kernel(
    const float* __restrict__ w_gate, const float* __restrict__ w_up)
{
    const int e = blockIdx.y;
    const int nT = d_expert_count[e];
    if (nT == 0) return;
    const int start = d_expert_start[e];   // even
    const int warp = threadIdx.x >> 5;
    const int lane = threadIdx.x & 31;
    const int i0 = blockIdx.x * 8 + warp * 2;   // 2 inter rows per warp

    const float* wg0 = w_gate + ((size_t)e * NI + i0) * NH;
    const float* wg1 = wg0 + NH;
    const float* wu0 = w_up + ((size_t)e * NI + i0) * NH;
    const float* wu1 = wu0 + NH;

    for (int c = 0; c < nT; c += 8) {
        const int nc = (nT - c < 8) ? (nT - c) : 8;
        const int slot0 = start + c;   // even
        if      (nc <= 2) gateup_body<1>(nc, slot0, wg0, wg1, wu0, wu1, i0, lane);
        else if (nc <= 4) gateup_body<2>(nc, slot0, wg0, wg1, wu0, wu1, i0, lane);
        else if (nc <= 6) gateup_body<3>(nc, slot0, wg0, wg1, wu0, wu1, i0, lane);
        else              gateup_body<4>(nc, slot0, wg0, wg1, wu0, wu1, i0, lane);
    }
}

// ============================================================
// Kernel 3: down projection. One warp: 4 h-rows, P token-pairs,
// fully unrolled software-pipelined k-loop (11 iters).
// ============================================================
template<int P>
__device__ __forceinline__ void down_body(
    const int nc, const int slot0,
    const float* __restrict__ w0, const float* __restrict__ w1,
    const float* __restrict__ w2, const float* __restrict__ w3,
    const int h0, const int lane)
{
    constexpr int ITERS = NI / 4 / 32;   // 11, compile-time

    unsigned long long a0[P], a1[P], a2[P], a3[P];
#pragma unroll
    for (int p = 0; p < P; p++) { a0[p] = 0ull; a1[p] = 0ull; a2[p] = 0ull; a3[p] = 0ull; }

    const float4* __restrict__ r0 = (const float4*)w0;
    const float4* __restrict__ r1 = (const float4*)w1;
    const float4* __restrict__ r2 = (const float4*)w2;
    const float4* __restrict__ r3 = (const float4*)w3;

    const ulonglong2* __restrict__ xp[P];
#pragma unroll
    for (int p = 0; p < P; p++)
        xp[p] = (const ulonglong2*)(d_mixed2 + (size_t)(slot0 + 2 * p) * NI);

    float4 v0, v1, v2, v3;
    ulonglong2 xlo[P], xhi[P];
    {
        const int kq = lane;
        v0 = __ldg(&r0[kq]); v1 = __ldg(&r1[kq]);
        v2 = __ldg(&r2[kq]); v3 = __ldg(&r3[kq]);
#pragma unroll
        for (int p = 0; p < P; p++) {
            xlo[p] = __ldg(&xp[p][2 * kq]);
            xhi[p] = __ldg(&xp[p][2 * kq + 1]);
        }
    }

#pragma unroll
    for (int it = 0; it < ITERS; it++) {
        const float4 c0 = v0, c1 = v1, c2 = v2, c3 = v3;
        ulonglong2 cxlo[P], cxhi[P];
#pragma unroll
        for (int p = 0; p < P; p++) { cxlo[p] = xlo[p]; cxhi[p] = xhi[p]; }

        if (it + 1 < ITERS) {
            const int kq = lane + 32 * (it + 1);
            v0 = __ldg(&r0[kq]); v1 = __ldg(&r1[kq]);
            v2 = __ldg(&r2[kq]); v3 = __ldg(&r3[kq]);
#pragma unroll
            for (int p = 0; p < P; p++) {
                xlo[p] = __ldg(&xp[p][2 * kq]);
                xhi[p] = __ldg(&xp[p][2 * kq + 1]);
            }
        }

        const unsigned long long W0x = pk2(c0.x, c0.x), W0y = pk2(c0.y, c0.y),
                                 W0z = pk2(c0.z, c0.z), W0w = pk2(c0.w, c0.w);
        const unsigned long long W1x = pk2(c1.x, c1.x), W1y = pk2(c1.y, c1.y),
                                 W1z = pk2(c1.z, c1.z), W1w = pk2(c1.w, c1.w);
        const unsigned long long W2x = pk2(c2.x, c2.x), W2y = pk2(c2.y, c2.y),
                                 W2z = pk2(c2.z, c2.z), W2w = pk2(c2.w, c2.w);
        const unsigned long long W3x = pk2(c3.x, c3.x), W3y = pk2(c3.y, c3.y),
                                 W3z = pk2(c3.z, c3.z), W3w = pk2(c3.w, c3.w);
#pragma unroll
        for (int p = 0; p < P; p++) {
            a0[p] = fma2(W0x, cxlo[p].x, a0[p]); a0[p] = fma2(W0y, cxlo[p].y, a0[p]);
            a0[p] = fma2(W0z, cxhi[p].x, a0[p]); a0[p] = fma2(W0w, cxhi[p].y, a0[p]);
            a1[p] = fma2(W1x, cxlo[p].x, a1[p]); a1[p] = fma2(W1y, cxlo[p].y, a1[p]);
            a1[p] = fma2(W1z, cxhi[p].x, a1[p]); a1[p] = fma2(W1w, cxhi[p].y, a1[p]);
            a2[p] = fma2(W2x, cxlo[p].x, a2[p]); a2[p] = fma2(W2y, cxlo[p].y, a2[p]);
            a2[p] = fma2(W2z, cxhi[p].x, a2[p]); a2[p] = fma2(W2w, cxhi[p].y, a2[p]);
            a3[p] = fma2(W3x, cxlo[p].x, a3[p]); a3[p] = fma2(W3y, cxlo[p].y, a3[p]);
            a3[p] = fma2(W3z, cxhi[p].x, a3[p]); a3[p] = fma2(W3w, cxhi[p].y, a3[p]);
        }
    }

#pragma unroll
    for (int p = 0; p < P; p++) {
#pragma unroll
        for (int o = 16; o > 0; o >>= 1) {
            a0[p] = add2(a0[p], __shfl_down_sync(0xFFFFFFFFu, a0[p], o));
            a1[p] = add2(a1[p], __shfl_down_sync(0xFFFFFFFFu, a1[p], o));
            a2[p] = add2(a2[p], __shfl_down_sync(0xFFFFFFFFu, a2[p], o));
            a3[p] = add2(a3[p], __shfl_down_sync(0xFFFFFFFFu, a3[p], o));
        }
        if (lane == 0 && 2 * p < nc) {
            const int sA = slot0 + 2 * p;
            float vA, vB;
            float* poA = d_pair_out + (size_t)sA * NH + h0;
            float* poB = poA + NH;
            upk2(a0[p], vA, vB); poA[0] = vA; poB[0] = vB;
            upk2(a1[p], vA, vB); poA[1] = vA; poB[1] = vB;
            upk2(a2[p], vA, vB); poA[2] = vA; poB[2] = vB;
            upk2(a3[p], vA, vB); poA[3] = vA; poB[3] = vB;
        }
    }
}

__global__ void __launch_bounds__(128) down_kernel(const float* __restrict__ w_down)
{
    const int e = blockIdx.y;
    const int nT = d_expert_count[e];
    if (nT == 0) return;
    const int start = d_expert_start[e];
    const int warp = threadIdx.x >> 5;
    const int lane = threadIdx.x & 31;
    const int h0 = blockIdx.x * 16 + warp * 4;   // 4 hidden rows per warp

    const float* w0 = w_down + ((size_t)e * NH + h0) * NI;
    const float* w1 = w0 + NI;
    const float* w2 = w0 + 2 * NI;
    const float* w3 = w0 + 3 * NI;

    for (int c = 0; c < nT; c += 8) {
        const int nc = (nT - c < 8) ? (nT - c) : 8;
        const int slot0 = start + c;
        if      (nc <= 2) down_body<1>(nc, slot0, w0, w1, w2, w3, h0, lane);
        else if (nc <= 4) down_body<2>(nc, slot0, w0, w1, w2, w3, h0, lane);
        else if (nc <= 6) down_body<3>(nc, slot0, w0, w1, w2, w3, h0, lane);
        else              down_body<4>(nc, slot0, w0, w1, w2, w3, h0, lane);
    }
}

// ============================================================
// Kernel 4: weighted combine of the 4 routed pair outputs.
// ============================================================
__global__ void combine_kernel(float* __restrict__ out)
{
    const int idx = blockIdx.x * blockDim.x + threadIdx.x;  // [0, NT*NH)
    const int t = idx / NH;
    const int h = idx - t * NH;
    float s = 0.f;
#pragma unroll
    for (int k = 0; k < NK; k++) {
        const int p = d_pair_idx[t * NK + k];
        s = fmaf(d_topk_w[t * NK + k], d_pair_out[(size_t)p * NH + h], s);
    }
    out[idx] = s;
}

// ============================================================
extern "C" void kernel_launch(void* const* d_in, const int* in_sizes, int n_in,
                              void* d_out, int out_size)
{
    const float* x      = (const float*)d_in[0];
    const float* logits = (const float*)d_in[1];
    const float* wg     = (const float*)d_in[2];
    const float* wu     = (const float*)d_in[3];
    const float* wd     = (const float*)d_in[4];
    float* out = (float*)d_out;

    route_kernel<<<1, NT>>>(logits);
    gather_kernel<<<MAXSLOT, 128>>>(x);
    gateup_kernel<<<dim3(NI / 8, NE), 128>>>(wg, wu);
    down_kernel<<<dim3(NH / 16, NE), 128>>>(wd);
    combine_kernel<<<(NT * NH) / 256, 256>>>(out);
}